// round 9
// baseline (speedup 1.0000x reference)
#include <cuda_runtime.h>
#include <cuda_bf16.h>

#define GRID_N 4
#define WIN    3
#define NWIN   (GRID_N - WIN + 1)   // 2
#define NCELL  (GRID_N * GRID_N)    // 16

// ---- Fast path constants (B=128, H=W=512) ----
#define NBATCH   128
#define NSTRIPE  512                // 128 batches * 4 grid-rows (128 rows each)
#define CHUNK    256                // float4 per chunk (one warp-coalesced load/thread)
#define NCHUNKS  32768              // 8,388,608 float4 / 256   (FLOAT4 count!)
#define NCTA     592                // 148 SMs * 4 -> balanced
#define BASE     55                 // 32768 = 208*56 + 384*55
#define REM      208
#define SPLIT    (REM * (BASE + 1)) // 11648

// Per-stripe partials: [stripe][slot(3)][gx(4)]. A stripe (64 chunks) is
// covered by <= 3 CTA ranges (each 55-56 chunks); slot = CTA index relative
// to the stripe's first covering CTA -> unique writer per slot, no atomics.
__device__ float        g_part[NSTRIPE * 3 * 4];
__device__ unsigned int g_cnt[NBATCH];          // zero-init; reset each run
__device__ float        g_cell[4096 * NCELL];   // generic-fallback scratch

__device__ __forceinline__ int cta_of_chunk(int ch) {
    return ch < SPLIT ? ch / (BASE + 1) : REM + (ch - SPLIT) / BASE;
}

__global__ __launch_bounds__(256) void balanced_kernel(
        const float4* __restrict__ in, float* __restrict__ out) {
    int cta = blockIdx.x;
    int t   = threadIdx.x;

    int c0, c1;
    if (cta < REM) { c0 = cta * (BASE + 1); c1 = c0 + BASE + 1; }
    else           { c0 = SPLIT + (cta - REM) * BASE; c1 = c0 + BASE; }

    long long f0 = (long long)c0 * CHUNK;   // float4 index
    long long f1 = (long long)c1 * CHUNK;

    __shared__ float ws[8];

    long long f = f0;
    while (f < f1) {
        int stripe = (int)(f >> 14);                    // 16384 float4/stripe
        long long slimit = ((long long)stripe + 1) << 14;
        long long send = slimit < f1 ? slimit : f1;
        int iters = (int)((send - f) >> 8);             // 1..64 chunks

        // Thread t reads f + k*256 + t: (f+t) & 127 == t & 127, so the
        // float4-column group gx = (t>>5)&3 is constant & warp-uniform.
        const float4* p = in + f + t;
        float acc = 0.0f;
        int k = 0;
        for (; k + 8 <= iters; k += 8) {                // MLP = 8
            float4 v0 = p[0],    v1 = p[256],  v2 = p[512],  v3 = p[768];
            float4 v4 = p[1024], v5 = p[1280], v6 = p[1536], v7 = p[1792];
            acc += (v0.x + v0.y) + (v0.z + v0.w);
            acc += (v1.x + v1.y) + (v1.z + v1.w);
            acc += (v2.x + v2.y) + (v2.z + v2.w);
            acc += (v3.x + v3.y) + (v3.z + v3.w);
            acc += (v4.x + v4.y) + (v4.z + v4.w);
            acc += (v5.x + v5.y) + (v5.z + v5.w);
            acc += (v6.x + v6.y) + (v6.z + v6.w);
            acc += (v7.x + v7.y) + (v7.z + v7.w);
            p += 2048;
        }
        for (; k < iters; k++) {
            float4 v = p[0];
            acc += (v.x + v.y) + (v.z + v.w);
            p += 256;
        }

#pragma unroll
        for (int o = 16; o > 0; o >>= 1)
            acc += __shfl_down_sync(0xffffffffu, acc, o);
        if ((t & 31) == 0) ws[t >> 5] = acc;
        __syncthreads();

        if (t < 4) {
            // warps 0..7 have gx = warp & 3 -> cell partial = ws[gx]+ws[gx+4]
            int rel = cta - cta_of_chunk(stripe << 6);  // 0..2, unique slot
            g_part[stripe * 12 + rel * 4 + t] = ws[t] + ws[t + 4];
        }
        __syncthreads();                                // ws reuse guard
        f = send;
    }

    // Fused epilogue: last CTA to finish a batch computes its output.
    if (t == 0) {
        __threadfence();                                // publish partials
        int b0 = c0 >> 8;                               // 256 chunks/batch
        int b1 = (c1 - 1) >> 8;
        for (int b = b0; b <= b1; b++) {
            unsigned exp = (unsigned)(cta_of_chunk(b * 256 + 255)
                                    - cta_of_chunk(b * 256) + 1);
            unsigned old = atomicAdd(&g_cnt[b], 1u);
            if (old == exp - 1u) {
                __threadfence();                        // acquire
                float c[NCELL];
#pragma unroll
                for (int gy = 0; gy < 4; gy++) {
                    int stripe = b * 4 + gy;
                    int fc = stripe << 6;               // first chunk
                    int n_cov = cta_of_chunk(fc + 63) - cta_of_chunk(fc) + 1;
#pragma unroll
                    for (int gx = 0; gx < 4; gx++) {
                        float s = 0.0f;
                        for (int sl = 0; sl < n_cov; sl++)
                            s += __ldcg(&g_part[stripe * 12 + sl * 4 + gx]);
                        c[gy * 4 + gx] = s;
                    }
                }
                float win[NWIN * NWIN];
#pragma unroll
                for (int r = 0; r < NWIN; r++)
#pragma unroll
                    for (int q = 0; q < NWIN; q++) {
                        float s = 0.0f;
#pragma unroll
                        for (int dr = 0; dr < WIN; dr++)
#pragma unroll
                            for (int dc = 0; dc < WIN; dc++)
                                s += c[(r + dr) * GRID_N + (q + dc)];
                        win[r * NWIN + q] = s;
                    }
                float best = win[0];
                int bi = 0;
#pragma unroll
                for (int k2 = 1; k2 < NWIN * NWIN; k2++)
                    if (win[k2] > best) { best = win[k2]; bi = k2; }

                out[b * 2 + 0] = (float)(bi >> 1);      // row (float32!)
                out[b * 2 + 1] = (float)(bi & 1);       // col
                g_cnt[b] = 0u;                          // replay-safe reset
            }
        }
    }
}

// ---------------- Generic fallback (any square H=W, H%4==0) ----------------
__global__ __launch_bounds__(256) void cell_sum_kernel(
        const float* __restrict__ in, int HW, int W, int gh, int gw) {
    int blk  = blockIdx.x;
    int cell = blk & (NCELL - 1);
    int b    = blk >> 4;
    int gx = cell & (GRID_N - 1);
    int gy = cell >> 2;
    const float* base = in + (size_t)b * HW + (size_t)(gy * gh) * W + (size_t)gx * gw;
    int t = threadIdx.x;
    int n = gh * gw;
    float acc = 0.0f;
    for (int i = t; i < n; i += 256) {
        int r = i / gw;
        int c = i - r * gw;
        acc += base[(size_t)r * W + c];
    }
    __shared__ float sh[256];
    sh[t] = acc;
    __syncthreads();
#pragma unroll
    for (int s = 128; s > 0; s >>= 1) {
        if (t < s) sh[t] += sh[t + s];
        __syncthreads();
    }
    if (t == 0) g_cell[blk] = sh[0];
}

__global__ void select_kernel(float* __restrict__ out, int B) {
    int b = blockIdx.x * blockDim.x + threadIdx.x;
    if (b >= B) return;
    float c[NCELL];
#pragma unroll
    for (int i = 0; i < NCELL; i++) c[i] = g_cell[b * NCELL + i];
    float win[NWIN * NWIN];
#pragma unroll
    for (int r = 0; r < NWIN; r++)
#pragma unroll
        for (int q = 0; q < NWIN; q++) {
            float s = 0.0f;
#pragma unroll
            for (int dr = 0; dr < WIN; dr++)
#pragma unroll
                for (int dc = 0; dc < WIN; dc++)
                    s += c[(r + dr) * GRID_N + (q + dc)];
            win[r * NWIN + q] = s;
        }
    float best = win[0];
    int bi = 0;
#pragma unroll
    for (int k = 1; k < NWIN * NWIN; k++)
        if (win[k] > best) { best = win[k]; bi = k; }
    out[b * 2 + 0] = (float)(bi / NWIN);
    out[b * 2 + 1] = (float)(bi % NWIN);
}

extern "C" void kernel_launch(void* const* d_in, const int* in_sizes, int n_in,
                              void* d_out, int out_size) {
    int best_i = 0;
    for (int i = 1; i < n_in; i++)
        if (in_sizes[i] > in_sizes[best_i]) best_i = i;
    const float* in = (const float*)d_in[best_i];
    float* out = (float*)d_out;

    int B = out_size / 2;
    if (B < 1) B = 1;
    long long HW = (long long)in_sizes[best_i] / B;

    if (B == NBATCH && HW == 512LL * 512LL) {
        balanced_kernel<<<NCTA, 256>>>((const float4*)in, out);
    } else {
        if (B > 4096) B = 4096;
        int H = 1;
        while ((long long)(H + 1) * (H + 1) <= HW) H++;
        int W = H;
        cell_sum_kernel<<<B * NCELL, 256>>>(in, (int)HW, W, H / GRID_N, W / GRID_N);
        select_kernel<<<(B + 127) / 128, 128>>>(out, B);
    }
}

// round 10
// speedup vs baseline: 1.5714x; 1.5714x over previous
#include <cuda_runtime.h>
#include <cuda_bf16.h>

#define GRID_N 4
#define WIN    3
#define NWIN   (GRID_N - WIN + 1)   // 2
#define NCELL  (GRID_N * GRID_N)    // 16
#define B_MAX  4096

// ---------------- Fast path: H = W = 512 (proven R5 structure) -------------
// One block per batch, 1024 threads. Threads [64c, 64c+64) own cell c.
// Cell = 128x128 fp32 = 4096 float4; each warp lies fully inside one cell
// (2 warps/cell). Compile-time 64-iteration loop -> ptxas front-batches LDGs
// (high MLP_p1). __ldcs: streaming (evict-first) loads for the zero-reuse
// 128MB stream.
__global__ __launch_bounds__(1024) void fused_512_kernel(
        const float4* __restrict__ in, float* __restrict__ out) {
    int b = blockIdx.x;
    int t = threadIdx.x;
    int cell = t >> 6;
    int j    = t & 63;
    int gy = cell >> 2;
    int gx = cell & 3;

    const float4* base = in + (size_t)b * 65536 + gy * 16384 + gx * 32;

    float acc = 0.0f;
#pragma unroll 16
    for (int k = 0; k < 64; k++) {
        int i   = k * 64 + j;
        int row = i >> 5;
        int c4  = i & 31;
        float4 v = __ldcs(&base[row * 128 + c4]);   // streaming load
        acc += (v.x + v.y) + (v.z + v.w);
    }
#pragma unroll
    for (int o = 16; o > 0; o >>= 1)
        acc += __shfl_down_sync(0xffffffffu, acc, o);

    __shared__ float wsum[32];
    if ((t & 31) == 0) wsum[t >> 5] = acc;
    __syncthreads();

    __shared__ float csum[NCELL];
    if (t < NCELL) csum[t] = wsum[2 * t] + wsum[2 * t + 1];
    __syncthreads();

    if (t == 0) {
        float win[NWIN * NWIN];
#pragma unroll
        for (int r = 0; r < NWIN; r++)
#pragma unroll
            for (int q = 0; q < NWIN; q++) {
                float s = 0.0f;
#pragma unroll
                for (int dr = 0; dr < WIN; dr++)
#pragma unroll
                    for (int dc = 0; dc < WIN; dc++)
                        s += csum[(r + dr) * GRID_N + (q + dc)];
                win[r * NWIN + q] = s;
            }
        float best = win[0];
        int bi = 0;
#pragma unroll
        for (int k = 1; k < NWIN * NWIN; k++)
            if (win[k] > best) { best = win[k]; bi = k; }

        out[b * 2 + 0] = (float)(bi >> 1);   // row (float32 output)
        out[b * 2 + 1] = (float)(bi & 1);    // col
    }
}

// ---------------- Generic fallback (any square H=W, H%4==0) ----------------
__device__ float g_cell[B_MAX * NCELL];

__global__ __launch_bounds__(256) void cell_sum_kernel(
        const float* __restrict__ in, int HW, int W, int gh, int gw) {
    int blk  = blockIdx.x;
    int cell = blk & (NCELL - 1);
    int b    = blk >> 4;
    int gx = cell & (GRID_N - 1);
    int gy = cell >> 2;

    const float* base = in + (size_t)b * HW + (size_t)(gy * gh) * W + (size_t)gx * gw;

    int t = threadIdx.x;
    int n = gh * gw;
    float acc = 0.0f;
    for (int i = t; i < n; i += 256) {
        int r = i / gw;
        int c = i - r * gw;
        acc += base[(size_t)r * W + c];
    }
    __shared__ float sh[256];
    sh[t] = acc;
    __syncthreads();
#pragma unroll
    for (int s = 128; s > 0; s >>= 1) {
        if (t < s) sh[t] += sh[t + s];
        __syncthreads();
    }
    if (t == 0) g_cell[blk] = sh[0];
}

__global__ void select_kernel(float* __restrict__ out, int B) {
    int b = blockIdx.x * blockDim.x + threadIdx.x;
    if (b >= B) return;
    float c[NCELL];
#pragma unroll
    for (int i = 0; i < NCELL; i++) c[i] = g_cell[b * NCELL + i];

    float win[NWIN * NWIN];
#pragma unroll
    for (int r = 0; r < NWIN; r++)
#pragma unroll
        for (int q = 0; q < NWIN; q++) {
            float s = 0.0f;
#pragma unroll
            for (int dr = 0; dr < WIN; dr++)
#pragma unroll
                for (int dc = 0; dc < WIN; dc++)
                    s += c[(r + dr) * GRID_N + (q + dc)];
            win[r * NWIN + q] = s;
        }
    float best = win[0];
    int bi = 0;
#pragma unroll
    for (int k = 1; k < NWIN * NWIN; k++)
        if (win[k] > best) { best = win[k]; bi = k; }

    out[b * 2 + 0] = (float)(bi / NWIN);
    out[b * 2 + 1] = (float)(bi % NWIN);
}

extern "C" void kernel_launch(void* const* d_in, const int* in_sizes, int n_in,
                              void* d_out, int out_size) {
    int best_i = 0;
    for (int i = 1; i < n_in; i++)
        if (in_sizes[i] > in_sizes[best_i]) best_i = i;
    const float* in = (const float*)d_in[best_i];
    float* out = (float*)d_out;

    int B = out_size / 2;
    if (B < 1) B = 1;
    long long HW = (long long)in_sizes[best_i] / B;

    if (HW == 512LL * 512LL) {
        fused_512_kernel<<<B, 1024>>>((const float4*)in, out);
    } else {
        if (B > B_MAX) B = B_MAX;
        int H = 1;
        while ((long long)(H + 1) * (H + 1) <= HW) H++;
        int W = H;
        cell_sum_kernel<<<B * NCELL, 256>>>(in, (int)HW, W, H / GRID_N, W / GRID_N);
        select_kernel<<<(B + 127) / 128, 128>>>(out, B);
    }
}